// round 1
// baseline (speedup 1.0000x reference)
#include <cuda_runtime.h>
#include <cuda_fp16.h>
#include <cstdint>

#define N_DIM  2048
#define T_SEQ  8192
#define G_DIM  6144
#define NBLK   128     // persistent blocks (1 per SM, all resident)
#define NTHR   512
#define NWARP  16
#define PB     16      // output elements per block
#define NFRAG  6       // n-fragments of 8 cols (48 cols per block)
#define KFRAG  8       // k-fragments of 16 per warp (128 k per warp)

// ---- scratch (device globals: allocation-free rule) ----
__device__ __half        g_x16[(size_t)T_SEQ * N_DIM];          // 32 MB
__device__ __half        g_WxT16[(size_t)G_DIM * N_DIM];        // 25 MB (transposed: [n][k])
__device__ float         g_gx[(size_t)T_SEQ * G_DIM];           // 192 MB
__device__ unsigned int  g_whpack[NBLK * NWARP * NFRAG * KFRAG * 32 * 2]; // 25 MB packed B-frags
__device__ __half        g_h16[2][N_DIM];                       // double-buffered h
__device__ unsigned int  g_ctr;                                 // grid barrier counter

// ---------------- reset ----------------
__global__ void reset_k() {
    if (threadIdx.x == 0) g_ctr = 0u;
    for (int i = threadIdx.x; i < 2 * N_DIM; i += blockDim.x)
        ((__half*)g_h16)[i] = __float2half(0.f);
}

// ---------------- convert x -> fp16 ----------------
__global__ void conv_x(const float* __restrict__ x) {
    const float2* x2 = (const float2*)x;
    __half2* o = (__half2*)g_x16;
    size_t n = (size_t)T_SEQ * N_DIM / 2;
    for (size_t i = blockIdx.x * (size_t)blockDim.x + threadIdx.x; i < n;
         i += (size_t)gridDim.x * blockDim.x)
        o[i] = __float22half2_rn(x2[i]);
}

// ------------- convert+transpose Wx -> WxT fp16 [n][k] -------------
__global__ void conv_wxt(const float* __restrict__ Wx) {
    size_t idx = blockIdx.x * (size_t)blockDim.x + threadIdx.x; // over K*G
    if (idx >= (size_t)N_DIM * G_DIM) return;
    int k = (int)(idx / G_DIM);
    int j = (int)(idx % G_DIM);
    g_WxT16[(size_t)j * N_DIM + k] = __float2half(Wx[idx]);
}

// ------------- pack Wh into per-block mma B fragments (fp16) -------------
// pidx = ((((b*16 + w)*6 + nf)*8 + kf)*32 + lane)*2 + r
__global__ void pack_wh(const float* __restrict__ Wh) {
    int idx = blockIdx.x * blockDim.x + threadIdx.x;
    if (idx >= NBLK * NWARP * NFRAG * KFRAG * 32 * 2) return;
    int r    = idx & 1;
    int l    = (idx >> 1) & 31;
    int kf   = (idx >> 6) & 7;
    int rest = idx >> 9;           // (b*16 + w)*6 + nf
    int nf   = rest % 6;
    int bw   = rest / 6;
    int w    = bw & 15;
    int b    = bw >> 4;
    int tid  = l & 3, gid = l >> 2;
    int grp  = nf >> 1;                                  // 0:z 1:r 2:n
    int j    = grp * N_DIM + b * PB + (nf & 1) * 8 + gid; // global column
    int k    = w * 128 + kf * 16 + r * 8 + 2 * tid;       // global k
    __half2 h;
    h.x = __float2half(Wh[(size_t)k * G_DIM + j]);
    h.y = __float2half(Wh[(size_t)(k + 1) * G_DIM + j]);
    g_whpack[idx] = *(unsigned int*)&h;
}

// ---------------- gx = x @ Wx + b  (fp16 mma, fp32 accum) ----------------
__global__ void __launch_bounds__(256) gemm_gx(const float* __restrict__ bias) {
    __shared__ __half As[128 * 40];
    __shared__ __half Bs[128 * 40];
    const int m0 = blockIdx.y * 128, n0 = blockIdx.x * 128;
    const int t = threadIdx.x, w = t >> 5, l = t & 31, tid = l & 3, gid = l >> 2;
    const int wm = w & 3, wn = w >> 2;
    float acc[2][8][4];
#pragma unroll
    for (int mt = 0; mt < 2; ++mt)
#pragma unroll
        for (int nt = 0; nt < 8; ++nt)
#pragma unroll
            for (int q = 0; q < 4; ++q) acc[mt][nt][q] = 0.f;

    for (int kt = 0; kt < N_DIM; kt += 32) {
        {
            int r = t >> 2, c = (t & 3) * 8;
            *(uint4*)(As + r * 40 + c)        = *(const uint4*)(g_x16  + (size_t)(m0 + r)      * N_DIM + kt + c);
            *(uint4*)(As + (r + 64) * 40 + c) = *(const uint4*)(g_x16  + (size_t)(m0 + r + 64) * N_DIM + kt + c);
            *(uint4*)(Bs + r * 40 + c)        = *(const uint4*)(g_WxT16 + (size_t)(n0 + r)      * N_DIM + kt + c);
            *(uint4*)(Bs + (r + 64) * 40 + c) = *(const uint4*)(g_WxT16 + (size_t)(n0 + r + 64) * N_DIM + kt + c);
        }
        __syncthreads();
#pragma unroll
        for (int s = 0; s < 2; ++s) {
            const int ko = s * 16;
            unsigned a[2][4];
#pragma unroll
            for (int mt = 0; mt < 2; ++mt) {
                int rb = wm * 32 + mt * 16;
                a[mt][0] = *(const unsigned*)(As + (rb + gid)     * 40 + ko + 2 * tid);
                a[mt][1] = *(const unsigned*)(As + (rb + gid + 8) * 40 + ko + 2 * tid);
                a[mt][2] = *(const unsigned*)(As + (rb + gid)     * 40 + ko + 2 * tid + 8);
                a[mt][3] = *(const unsigned*)(As + (rb + gid + 8) * 40 + ko + 2 * tid + 8);
            }
#pragma unroll
            for (int nt = 0; nt < 8; ++nt) {
                int cb = wn * 64 + nt * 8 + gid;
                unsigned b0 = *(const unsigned*)(Bs + cb * 40 + ko + 2 * tid);
                unsigned b1 = *(const unsigned*)(Bs + cb * 40 + ko + 2 * tid + 8);
#pragma unroll
                for (int mt = 0; mt < 2; ++mt) {
                    asm volatile(
                        "mma.sync.aligned.m16n8k16.row.col.f32.f16.f16.f32 "
                        "{%0,%1,%2,%3},{%4,%5,%6,%7},{%8,%9},{%0,%1,%2,%3};"
                        : "+f"(acc[mt][nt][0]), "+f"(acc[mt][nt][1]),
                          "+f"(acc[mt][nt][2]), "+f"(acc[mt][nt][3])
                        : "r"(a[mt][0]), "r"(a[mt][1]), "r"(a[mt][2]), "r"(a[mt][3]),
                          "r"(b0), "r"(b1));
                }
            }
        }
        __syncthreads();
    }
#pragma unroll
    for (int mt = 0; mt < 2; ++mt)
#pragma unroll
        for (int nt = 0; nt < 8; ++nt) {
            int row = m0 + wm * 32 + mt * 16 + gid;
            int col = n0 + wn * 64 + nt * 8 + 2 * tid;
            float b0v = __ldg(bias + col), b1v = __ldg(bias + col + 1);
            g_gx[(size_t)row * G_DIM + col]           = acc[mt][nt][0] + b0v;
            g_gx[(size_t)row * G_DIM + col + 1]       = acc[mt][nt][1] + b1v;
            g_gx[(size_t)(row + 8) * G_DIM + col]     = acc[mt][nt][2] + b0v;
            g_gx[(size_t)(row + 8) * G_DIM + col + 1] = acc[mt][nt][3] + b1v;
        }
}

// ---------------- persistent GRU scan ----------------
// dynamic smem layout (bytes):
//   [0,196608)      packed Wh fragments (49152 u32)
//   [196608,200704) h16 broadcast (1024 u32)
//   [200704,203776) red[16][48] f32
//   [203776,203968) gh[48] f32
//   [203968,204032) h32[16] f32
#define SMEM_SCAN 204032

__global__ void __launch_bounds__(NTHR, 1) gru_scan(float* __restrict__ out) {
    extern __shared__ unsigned char smem[];
    unsigned int* wp   = (unsigned int*)smem;
    unsigned int* h16s = (unsigned int*)(smem + 196608);
    float*        red  = (float*)(smem + 200704);
    float*        gh   = (float*)(smem + 203776);
    float*        h32  = (float*)(smem + 203968);

    const int b  = blockIdx.x;
    const int t0 = threadIdx.x;
    const int w  = t0 >> 5, l = t0 & 31, tid = l & 3, gid = l >> 2;
    const int i0 = b * PB;

    // stage this block's weight fragments into smem (once)
    {
        const uint4* src = (const uint4*)(g_whpack + (size_t)b * 49152);
        uint4* dst = (uint4*)wp;
        for (int i = t0; i < 49152 / 4; i += NTHR) dst[i] = src[i];
    }
    if (t0 < PB) h32[t0] = 0.f;
    __syncthreads();

    unsigned int* ctrp = &g_ctr;

    for (int t = 0; t < T_SEQ; ++t) {
        // broadcast h (fp16) into smem
        const unsigned* hg = (const unsigned*)g_h16[t & 1];
        for (int i = t0; i < N_DIM / 2; i += NTHR) h16s[i] = __ldg(hg + i);
        // prefetch gx for this block's outputs
        float xz = 0.f, xr = 0.f, xn = 0.f;
        if (t0 < PB) {
            const float* gxr = g_gx + (size_t)t * G_DIM;
            xz = __ldg(gxr + i0 + t0);
            xr = __ldg(gxr + N_DIM + i0 + t0);
            xn = __ldg(gxr + 2 * N_DIM + i0 + t0);
        }
        __syncthreads();

        float acc[NFRAG][4];
#pragma unroll
        for (int nf = 0; nf < NFRAG; ++nf)
#pragma unroll
            for (int q = 0; q < 4; ++q) acc[nf][q] = 0.f;

#pragma unroll
        for (int kf = 0; kf < KFRAG; ++kf) {
            unsigned a0 = h16s[w * 64 + kf * 8 + tid];
            unsigned a2 = h16s[w * 64 + kf * 8 + 4 + tid];
#pragma unroll
            for (int nf = 0; nf < NFRAG; ++nf) {
                const uint2 bb = *(const uint2*)(wp + (size_t)(((w * NFRAG + nf) * KFRAG + kf) * 32 + l) * 2);
                asm volatile(
                    "mma.sync.aligned.m16n8k16.row.col.f32.f16.f16.f32 "
                    "{%0,%1,%2,%3},{%4,%5,%6,%7},{%8,%9},{%0,%1,%2,%3};"
                    : "+f"(acc[nf][0]), "+f"(acc[nf][1]), "+f"(acc[nf][2]), "+f"(acc[nf][3])
                    : "r"(a0), "r"(0u), "r"(a2), "r"(0u), "r"(bb.x), "r"(bb.y));
            }
        }
        if (gid == 0) {
#pragma unroll
            for (int nf = 0; nf < NFRAG; ++nf) {
                red[w * 48 + nf * 8 + 2 * tid]     = acc[nf][0];
                red[w * 48 + nf * 8 + 2 * tid + 1] = acc[nf][1];
            }
        }
        __syncthreads();
        if (t0 < 48) {
            float s = 0.f;
#pragma unroll
            for (int ww = 0; ww < NWARP; ++ww) s += red[ww * 48 + t0];
            gh[t0] = s;
        }
        __syncthreads();
        if (t0 < PB) {
            float z    = 1.f / (1.f + expf(-(xz + gh[t0])));
            float r    = 1.f / (1.f + expf(-(xr + gh[16 + t0])));
            float cand = tanhf(xn + r * gh[32 + t0]);
            float hp   = h32[t0];
            float hn   = hp + z * (cand - hp);
            h32[t0] = hn;
            out[(size_t)t * N_DIM + i0 + t0] = hn;
            ((__half*)g_h16[(t + 1) & 1])[i0 + t0] = __float2half(hn);
        }
        __syncthreads();
        if (t < T_SEQ - 1) {
            if (t0 == 0) {
                unsigned target = (unsigned)(NBLK * (t + 1));
                asm volatile("red.release.gpu.add.u32 [%0], %1;" :: "l"(ctrp), "r"(1u) : "memory");
                unsigned v;
                do {
                    asm volatile("ld.acquire.gpu.u32 %0, [%1];" : "=r"(v) : "l"(ctrp) : "memory");
                } while (v < target);
            }
            __syncthreads();
        }
    }
}

// ---------------- launcher ----------------
extern "C" void kernel_launch(void* const* d_in, const int* in_sizes, int n_in,
                              void* d_out, int out_size) {
    const float* x    = (const float*)d_in[0];
    const float* Wx   = (const float*)d_in[1];
    const float* Wh   = (const float*)d_in[2];
    const float* bias = (const float*)d_in[3];
    float* out = (float*)d_out;

    cudaFuncSetAttribute(gru_scan, cudaFuncAttributeMaxDynamicSharedMemorySize, SMEM_SCAN);

    reset_k<<<1, 256>>>();
    conv_x<<<4096, 256>>>(x);
    {
        int n = N_DIM * G_DIM;
        conv_wxt<<<(n + 255) / 256, 256>>>(Wx);
    }
    {
        int n = NBLK * NWARP * NFRAG * KFRAG * 32 * 2;
        pack_wh<<<(n + 255) / 256, 256>>>(Wh);
    }
    gemm_gx<<<dim3(G_DIM / 128, T_SEQ / 128), 256>>>(bias);
    gru_scan<<<NBLK, NTHR, SMEM_SCAN>>>(out);
}